// round 7
// baseline (speedup 1.0000x reference)
#include <cuda_runtime.h>
#include <cuda_bf16.h>
#include <cstdint>

#define T_TOK 32768
#define H_DIM 2048
#define I_DIM 768

using bf16 = __nv_bfloat16;

// ---------------- static device scratch ------------------------------------
__device__ bf16 g_Ahi[(size_t)T_TOK * H_DIM];
__device__ bf16 g_Alo[(size_t)T_TOK * H_DIM];
__device__ bf16 g_Wgu_hi[(size_t)2 * I_DIM * H_DIM];   // w_gate_up^T  [2I, H]
__device__ bf16 g_Wgu_lo[(size_t)2 * I_DIM * H_DIM];
__device__ bf16 g_Wd_hi[(size_t)H_DIM * I_DIM];        // w_down^T     [H, I]
__device__ bf16 g_Wd_lo[(size_t)H_DIM * I_DIM];
__device__ bf16 g_Xhi[(size_t)T_TOK * I_DIM];          // silu(g)*u    [T, I]
__device__ bf16 g_Xlo[(size_t)T_TOK * I_DIM];

// ---------------- helpers ----------------------------------------------------
__device__ __forceinline__ uint32_t smem_u32(const void* p) {
    return (uint32_t)__cvta_generic_to_shared(p);
}
__device__ __forceinline__ void cp16(uint32_t dst, const void* src) {
    asm volatile("cp.async.cg.shared.global [%0], [%1], 16;" :: "r"(dst), "l"(src));
}
__device__ __forceinline__ void cp_commit() {
    asm volatile("cp.async.commit_group;" ::: "memory");
}
template <int N>
__device__ __forceinline__ void cp_wait() {
    asm volatile("cp.async.wait_group %0;" :: "n"(N) : "memory");
}
__device__ __forceinline__ void ldsm_x4(uint32_t* r, uint32_t addr) {
    asm volatile("ldmatrix.sync.aligned.m8n8.x4.shared.b16 {%0,%1,%2,%3}, [%4];"
                 : "=r"(r[0]), "=r"(r[1]), "=r"(r[2]), "=r"(r[3]) : "r"(addr));
}
__device__ __forceinline__ void mma16816(float* d, const uint32_t* a,
                                         uint32_t b0, uint32_t b1) {
    asm volatile(
        "mma.sync.aligned.m16n8k16.row.col.f32.bf16.bf16.f32 "
        "{%0,%1,%2,%3}, {%4,%5,%6,%7}, {%8,%9}, {%0,%1,%2,%3};"
        : "+f"(d[0]), "+f"(d[1]), "+f"(d[2]), "+f"(d[3])
        : "r"(a[0]), "r"(a[1]), "r"(a[2]), "r"(a[3]), "r"(b0), "r"(b1));
}
__device__ __forceinline__ uint32_t pk2(bf16 a, bf16 b) {
    __nv_bfloat162 t; t.x = a; t.y = b;
    return *reinterpret_cast<uint32_t*>(&t);
}
__device__ __forceinline__ void split1(float a, bf16& h, bf16& l) {
    h = __float2bfloat16_rn(a);
    l = __float2bfloat16_rn(a - __bfloat162float(h));
}

// SMEM stage layout: BK=16 (32B data/row), row stride 48B (12 words) ->
// ldmatrix 8-row bank spread {0,12,24,4,16,28,8,20} x4 words: conflict-free.
//   Ahi @0 (128x48=6144), Alo @6144, Bhi @12288, Blo @18432
#define ROWB        48
#define ARR_BYTES   6144
#define STAGE_BYTES 24576
#define NSTAGE      4
#define SMEM_BYTES  (NSTAGE * STAGE_BYTES)

// ============================================================================
// GEMM1: hidden[T,H] x Wgu^T[2I,H] -> silu(gate)*up -> Xhi/Xlo [T,I]
// CTA: 128 tokens x 64 I-cols (gate + up). 8 warps (2 m x 4 n).
// ============================================================================
__device__ __forceinline__ void g1_load_stage(
    uint32_t SB, int k0, int bm, int nt,
    const bf16* __restrict__ Ahi, const bf16* __restrict__ Alo,
    const bf16* __restrict__ Wh,  const bf16* __restrict__ Wl, int tid)
{
    {   // A: 128 rows x 2 chunks of 16B (hi + lo)
        int row = tid >> 1, kc = tid & 1;
        uint32_t d = SB + row * ROWB + kc * 16;
        size_t gof = (size_t)(bm + row) * H_DIM + k0 + kc * 8;
        cp16(d,             Ahi + gof);
        cp16(d + ARR_BYTES, Alo + gof);
    }
    {   // B: 64 gate + 64 up rows x 2 chunks (hi + lo)
        int row = tid >> 1, kc = tid & 1;
        int gr = (row < 64) ? (nt * 64 + row) : (I_DIM + nt * 64 + row - 64);
        uint32_t d = SB + 12288 + row * ROWB + kc * 16;
        size_t gof = (size_t)gr * H_DIM + k0 + kc * 8;
        cp16(d,             Wh + gof);
        cp16(d + ARR_BYTES, Wl + gof);
    }
}

__global__ __launch_bounds__(256, 2)
void gemm1_k(const bf16* __restrict__ Ahi, const bf16* __restrict__ Alo,
             const bf16* __restrict__ Wh,  const bf16* __restrict__ Wl,
             bf16* __restrict__ Xhi, bf16* __restrict__ Xlo)
{
    extern __shared__ char smem[];
    const uint32_t sb = smem_u32(smem);
    const int tid = threadIdx.x, wid = tid >> 5, lane = tid & 31;
    const int warp_m = wid & 1, warp_n = wid >> 1;
    const int nt = blockIdx.x;                  // 0..11 (64 I-cols each)
    const int bm = blockIdx.y * 128;
    const int NITER = H_DIM / 16;               // 128

    float accg[4][2][4], accu[4][2][4];
#pragma unroll
    for (int mi = 0; mi < 4; mi++)
#pragma unroll
        for (int ni = 0; ni < 2; ni++)
#pragma unroll
            for (int v = 0; v < 4; v++) { accg[mi][ni][v] = 0.f; accu[mi][ni][v] = 0.f; }

    g1_load_stage(sb, 0, bm, nt, Ahi, Alo, Wh, Wl, tid); cp_commit();
    g1_load_stage(sb + STAGE_BYTES, 16, bm, nt, Ahi, Alo, Wh, Wl, tid); cp_commit();
    g1_load_stage(sb + 2 * STAGE_BYTES, 32, bm, nt, Ahi, Alo, Wh, Wl, tid); cp_commit();

    const int arow = lane & 15;
    const int acol = (lane >> 4) * 16;
    const int brow = (lane & 7) + ((lane >> 4) << 3);
    const int bcol = ((lane >> 3) & 1) * 16;

    for (int it = 0; it < NITER; ++it) {
        cp_wait<2>();
        __syncthreads();     // single barrier per iter (stage it-1 fully consumed)
        if (it + 3 < NITER) {
            g1_load_stage(sb + ((it + 3) & 3) * STAGE_BYTES, (it + 3) * 16,
                          bm, nt, Ahi, Alo, Wh, Wl, tid);
        }
        cp_commit();

        uint32_t SB = sb + (it & 3) * STAGE_BYTES;
        // B fragments (gate hi/lo, up hi/lo)
        uint32_t rb = SB + 12288 + (warp_n * 16 + brow) * ROWB + bcol;
        uint32_t bgh[4], bgl[4], buh[4], bul[4];
        ldsm_x4(bgh, rb);
        ldsm_x4(bgl, rb + ARR_BYTES);
        ldsm_x4(buh, rb + 64 * ROWB);
        ldsm_x4(bul, rb + 64 * ROWB + ARR_BYTES);

        // A hi fragments (reused for lo)
        uint32_t af[4][4];
#pragma unroll
        for (int mi = 0; mi < 4; mi++) {
            uint32_t ra = SB + (warp_m * 64 + mi * 16 + arow) * ROWB + acol;
            ldsm_x4(af[mi], ra);
        }
        // pass 1: hi * B_hi
#pragma unroll
        for (int mi = 0; mi < 4; mi++)
#pragma unroll
            for (int ni = 0; ni < 2; ni++) {
                mma16816(accg[mi][ni], af[mi], bgh[ni*2], bgh[ni*2+1]);
                mma16816(accu[mi][ni], af[mi], buh[ni*2], buh[ni*2+1]);
            }
        // pass 2: hi * B_lo
#pragma unroll
        for (int mi = 0; mi < 4; mi++)
#pragma unroll
            for (int ni = 0; ni < 2; ni++) {
                mma16816(accg[mi][ni], af[mi], bgl[ni*2], bgl[ni*2+1]);
                mma16816(accu[mi][ni], af[mi], bul[ni*2], bul[ni*2+1]);
            }
        // reload A lo into same regs
#pragma unroll
        for (int mi = 0; mi < 4; mi++) {
            uint32_t ra = SB + (warp_m * 64 + mi * 16 + arow) * ROWB + acol;
            ldsm_x4(af[mi], ra + ARR_BYTES);
        }
        // pass 3: lo * B_hi
#pragma unroll
        for (int mi = 0; mi < 4; mi++)
#pragma unroll
            for (int ni = 0; ni < 2; ni++) {
                mma16816(accg[mi][ni], af[mi], bgh[ni*2], bgh[ni*2+1]);
                mma16816(accu[mi][ni], af[mi], buh[ni*2], buh[ni*2+1]);
            }
    }

    // epilogue: silu(gate)*up, split, store packed pairs
    const int g = lane >> 2, t = lane & 3;
#pragma unroll
    for (int mi = 0; mi < 4; mi++)
#pragma unroll
        for (int ni = 0; ni < 2; ni++) {
            int col = nt * 64 + warp_n * 16 + ni * 8 + t * 2;
            int row0 = bm + warp_m * 64 + mi * 16 + g;
#pragma unroll
            for (int h = 0; h < 2; h++) {
                int row = row0 + h * 8;
                float g0 = accg[mi][ni][h*2],   g1 = accg[mi][ni][h*2+1];
                float u0 = accu[mi][ni][h*2],   u1 = accu[mi][ni][h*2+1];
                float x0 = u0 * g0 / (1.0f + __expf(-g0));
                float x1 = u1 * g1 / (1.0f + __expf(-g1));
                bf16 h0, l0, h1, l1;
                split1(x0, h0, l0); split1(x1, h1, l1);
                size_t o = (size_t)row * I_DIM + col;
                *reinterpret_cast<uint32_t*>(Xhi + o) = pk2(h0, h1);
                *reinterpret_cast<uint32_t*>(Xlo + o) = pk2(l0, l1);
            }
        }
}

// ============================================================================
// GEMM2: X[T,I] x Wd^T[H,I] -> out[T,H] fp32
// CTA: 128 tokens x 128 H-cols. 8 warps (2 m x 4 n), warp 64x32.
// ============================================================================
__device__ __forceinline__ void g2_load_stage(
    uint32_t SB, int k0, int bm, int bn,
    const bf16* __restrict__ Xh, const bf16* __restrict__ Xl,
    const bf16* __restrict__ Dh, const bf16* __restrict__ Dl, int tid)
{
    {
        int row = tid >> 1, kc = tid & 1;
        uint32_t d = SB + row * ROWB + kc * 16;
        size_t gof = (size_t)(bm + row) * I_DIM + k0 + kc * 8;
        cp16(d,             Xh + gof);
        cp16(d + ARR_BYTES, Xl + gof);
    }
    {
        int row = tid >> 1, kc = tid & 1;
        uint32_t d = SB + 12288 + row * ROWB + kc * 16;
        size_t gof = (size_t)(bn + row) * I_DIM + k0 + kc * 8;
        cp16(d,             Dh + gof);
        cp16(d + ARR_BYTES, Dl + gof);
    }
}

__global__ __launch_bounds__(256, 2)
void gemm2_k(const bf16* __restrict__ Xh, const bf16* __restrict__ Xl,
             const bf16* __restrict__ Dh, const bf16* __restrict__ Dl,
             float* __restrict__ out)
{
    extern __shared__ char smem[];
    const uint32_t sb = smem_u32(smem);
    const int tid = threadIdx.x, wid = tid >> 5, lane = tid & 31;
    const int warp_m = wid & 1, warp_n = wid >> 1;
    const int bn = blockIdx.x * 128;
    const int bm = blockIdx.y * 128;
    const int NITER = I_DIM / 16;               // 48

    float acc[4][4][4];
#pragma unroll
    for (int mi = 0; mi < 4; mi++)
#pragma unroll
        for (int ni = 0; ni < 4; ni++)
#pragma unroll
            for (int v = 0; v < 4; v++) acc[mi][ni][v] = 0.f;

    g2_load_stage(sb, 0, bm, bn, Xh, Xl, Dh, Dl, tid); cp_commit();
    g2_load_stage(sb + STAGE_BYTES, 16, bm, bn, Xh, Xl, Dh, Dl, tid); cp_commit();
    g2_load_stage(sb + 2 * STAGE_BYTES, 32, bm, bn, Xh, Xl, Dh, Dl, tid); cp_commit();

    const int arow = lane & 15;
    const int acol = (lane >> 4) * 16;
    const int brow = (lane & 7) + ((lane >> 4) << 3);
    const int bcol = ((lane >> 3) & 1) * 16;

    for (int it = 0; it < NITER; ++it) {
        cp_wait<2>();
        __syncthreads();
        if (it + 3 < NITER) {
            g2_load_stage(sb + ((it + 3) & 3) * STAGE_BYTES, (it + 3) * 16,
                          bm, bn, Xh, Xl, Dh, Dl, tid);
        }
        cp_commit();

        uint32_t SB = sb + (it & 3) * STAGE_BYTES;
        uint32_t bh[8], bl[8];
#pragma unroll
        for (int bq = 0; bq < 2; bq++) {
            uint32_t rb = SB + 12288 + (warp_n * 32 + bq * 16 + brow) * ROWB + bcol;
            ldsm_x4(&bh[bq*4], rb);
            ldsm_x4(&bl[bq*4], rb + ARR_BYTES);
        }
        uint32_t af[4][4];
#pragma unroll
        for (int mi = 0; mi < 4; mi++) {
            uint32_t ra = SB + (warp_m * 64 + mi * 16 + arow) * ROWB + acol;
            ldsm_x4(af[mi], ra);
        }
        // pass 1: hi * B_hi
#pragma unroll
        for (int mi = 0; mi < 4; mi++)
#pragma unroll
            for (int ni = 0; ni < 4; ni++)
                mma16816(acc[mi][ni], af[mi], bh[ni*2], bh[ni*2+1]);
        // pass 2: hi * B_lo
#pragma unroll
        for (int mi = 0; mi < 4; mi++)
#pragma unroll
            for (int ni = 0; ni < 4; ni++)
                mma16816(acc[mi][ni], af[mi], bl[ni*2], bl[ni*2+1]);
        // reload A lo
#pragma unroll
        for (int mi = 0; mi < 4; mi++) {
            uint32_t ra = SB + (warp_m * 64 + mi * 16 + arow) * ROWB + acol;
            ldsm_x4(af[mi], ra + ARR_BYTES);
        }
        // pass 3: lo * B_hi
#pragma unroll
        for (int mi = 0; mi < 4; mi++)
#pragma unroll
            for (int ni = 0; ni < 4; ni++)
                mma16816(acc[mi][ni], af[mi], bh[ni*2], bh[ni*2+1]);
    }

    const int g = lane >> 2, t = lane & 3;
#pragma unroll
    for (int mi = 0; mi < 4; mi++)
#pragma unroll
        for (int ni = 0; ni < 4; ni++) {
            int col = bn + warp_n * 32 + ni * 8 + t * 2;
            int row0 = bm + warp_m * 64 + mi * 16 + g;
            float2 v0 = make_float2(acc[mi][ni][0], acc[mi][ni][1]);
            float2 v1 = make_float2(acc[mi][ni][2], acc[mi][ni][3]);
            *reinterpret_cast<float2*>(out + (size_t)row0 * H_DIM + col) = v0;
            *reinterpret_cast<float2*>(out + (size_t)(row0 + 8) * H_DIM + col) = v1;
        }
}

// ---------------- prep kernels ----------------------------------------------
__global__ void split_hidden_k(const float* __restrict__ in,
                               bf16* __restrict__ hi, bf16* __restrict__ lo)
{
    size_t i = (size_t)blockIdx.x * blockDim.x + threadIdx.x;
    float4 v = reinterpret_cast<const float4*>(in)[i];
    bf16 h0, l0, h1, l1, h2, l2, h3, l3;
    split1(v.x, h0, l0); split1(v.y, h1, l1);
    split1(v.z, h2, l2); split1(v.w, h3, l3);
    uint2 ph; ph.x = pk2(h0, h1); ph.y = pk2(h2, h3);
    uint2 pl; pl.x = pk2(l0, l1); pl.y = pk2(l2, l3);
    reinterpret_cast<uint2*>(hi)[i] = ph;
    reinterpret_cast<uint2*>(lo)[i] = pl;
}

__global__ void transpose_split_k(const float* __restrict__ in,
                                  bf16* __restrict__ ohi, bf16* __restrict__ olo,
                                  int R, int C)
{
    __shared__ float t[32][33];
    int bx = blockIdx.x * 32, by = blockIdx.y * 32;
    int tx = threadIdx.x, ty = threadIdx.y;
#pragma unroll
    for (int j = 0; j < 32; j += 8)
        t[ty + j][tx] = in[(size_t)(by + ty + j) * C + bx + tx];
    __syncthreads();
#pragma unroll
    for (int j = 0; j < 32; j += 8) {
        float a = t[tx][ty + j];
        bf16 h, l; split1(a, h, l);
        size_t o = (size_t)(bx + ty + j) * R + by + tx;
        ohi[o] = h; olo[o] = l;
    }
}

// ---------------- host ------------------------------------------------------
extern "C" void kernel_launch(void* const* d_in, const int* in_sizes, int n_in,
                              void* d_out, int out_size)
{
    const float* hidden = (const float*)d_in[0];   // [T, H]
    const float* wgu    = (const float*)d_in[1];   // [H, 2I]
    const float* wd     = (const float*)d_in[2];   // [I, H]
    float* out = (float*)d_out;                    // [T, H]

    bf16 *Ahi, *Alo, *Wh, *Wl, *Dh, *Dl, *Xh, *Xl;
    cudaGetSymbolAddress((void**)&Ahi, g_Ahi);
    cudaGetSymbolAddress((void**)&Alo, g_Alo);
    cudaGetSymbolAddress((void**)&Wh,  g_Wgu_hi);
    cudaGetSymbolAddress((void**)&Wl,  g_Wgu_lo);
    cudaGetSymbolAddress((void**)&Dh,  g_Wd_hi);
    cudaGetSymbolAddress((void**)&Dl,  g_Wd_lo);
    cudaGetSymbolAddress((void**)&Xh,  g_Xhi);
    cudaGetSymbolAddress((void**)&Xl,  g_Xlo);

    cudaFuncSetAttribute(gemm1_k, cudaFuncAttributeMaxDynamicSharedMemorySize, SMEM_BYTES);
    cudaFuncSetAttribute(gemm2_k, cudaFuncAttributeMaxDynamicSharedMemorySize, SMEM_BYTES);

    split_hidden_k<<<(int)(((size_t)T_TOK * H_DIM / 4) / 256), 256>>>(hidden, Ahi, Alo);
    transpose_split_k<<<dim3(2 * I_DIM / 32, H_DIM / 32), dim3(32, 8)>>>(wgu, Wh, Wl, H_DIM, 2 * I_DIM);
    transpose_split_k<<<dim3(H_DIM / 32, I_DIM / 32), dim3(32, 8)>>>(wd, Dh, Dl, I_DIM, H_DIM);

    gemm1_k<<<dim3(I_DIM / 64, T_TOK / 128), 256, SMEM_BYTES>>>(Ahi, Alo, Wh, Wl, Xh, Xl);
    gemm2_k<<<dim3(H_DIM / 128, T_TOK / 128), 256, SMEM_BYTES>>>(Xh, Xl, Dh, Dl, out);
}